// round 12
// baseline (speedup 1.0000x reference)
#include <cuda_runtime.h>
#include <math.h>
#include <float.h>
#include <string.h>

#define BATCH 64
#define NPTS  1024
#define KK    16
#define CH    64

typedef unsigned long long ull;

// ---------------- packed f32x2 helpers ------------------------------------------
__device__ __forceinline__ ull pk(float a, float b) {  // pack (a, b)
    ull r;
    asm("mov.b64 %0, {%1, %2};" : "=l"(r) : "f"(a), "f"(b));
    return r;
}
__device__ __forceinline__ void fma2(ull& d, ull a, ull b) {
    asm("fma.rn.f32x2 %0, %1, %2, %0;" : "+l"(d) : "l"(a), "l"(b));
}
__device__ __forceinline__ float2 upk(ull v) {
    float2 r;
    asm("mov.b64 {%0, %1}, %2;" : "=f"(r.x), "=f"(r.y) : "l"(v));
    return r;
}
__device__ __forceinline__ ull ld2(const float* p) {  // adjacent pair (p[0], p[1])
    ull r;
    memcpy(&r, p, 8);
    return r;
}

// ---------------- scratch (static device globals; no allocation) ----------------
__device__ __align__(16) float g_x1[BATCH * NPTS * CH];
__device__ __align__(16) float g_x2[BATCH * NPTS * CH];
__device__ __align__(16) float g_x3[BATCH * NPTS * CH];
__device__ __align__(16) float g_xt[BATCH * NPTS * CH];   // transposed features
__device__ __align__(16) float g_base[BATCH * NPTS * CH]; // b1 + x@w1a - x@w1b
__device__ __align__(16) float g_y[BATCH * NPTS * CH];    // x@w1b
__device__ int g_idx[BATCH * NPTS * KK];

// ---------------- warp bitonic sort of 32 (value,index) pairs, lex ascending ----
__device__ __forceinline__ void bitonic32(float& sv, int& si, int lane) {
#pragma unroll
    for (int size = 2; size <= 32; size <<= 1) {
#pragma unroll
        for (int stride = size >> 1; stride > 0; stride >>= 1) {
            float ov = __shfl_xor_sync(0xffffffffu, sv, stride);
            int oi = __shfl_xor_sync(0xffffffffu, si, stride);
            bool dirDesc = (lane & size) != 0;
            bool iAmLower = (lane & stride) == 0;
            bool wantSmaller = iAmLower != dirDesc;
            bool otherLess = (ov < sv) || (ov == sv && oi < si);
            if (wantSmaller == otherLess) { sv = ov; si = oi; }
        }
    }
}

// ---------------- warp top-16 selection from a 1024 row (exact lex) -------------
__device__ __forceinline__ void warp_select16(float* row, int lane,
                                              int* __restrict__ outp) {
    float v[32];
#pragma unroll
    for (int r = 0; r < 32; r++) v[r] = row[lane + 32 * r];

    float lv = v[0];
    int li = lane;
#pragma unroll
    for (int r = 1; r < 32; r++) {
        if (v[r] < lv) { lv = v[r]; li = lane + 32 * r; }
    }
    float sv = lv; int si = li;
    bitonic32(sv, si, lane);
    float Tv = __shfl_sync(0xffffffffu, sv, 15);
    int   Ti = __shfl_sync(0xffffffffu, si, 15);

    int cnt = 0;
#pragma unroll
    for (int r = 0; r < 32; r++) {
        int idx = lane + 32 * r;
        bool le = (v[r] < Tv) || (v[r] == Tv && idx <= Ti);
        cnt += le ? 1 : 0;
    }
    int total = __reduce_add_sync(0xffffffffu, cnt);

    if (total <= 32) {
        int pre = cnt;
#pragma unroll
        for (int o = 1; o < 32; o <<= 1) {
            int n = __shfl_up_sync(0xffffffffu, pre, o);
            if (lane >= o) pre += n;
        }
        pre -= cnt;
        float* candV = row;
        int* candI = (int*)(row + 32);
        int off = pre;
#pragma unroll
        for (int r = 0; r < 32; r++) {
            int idx = lane + 32 * r;
            bool le = (v[r] < Tv) || (v[r] == Tv && idx <= Ti);
            if (le) { candV[off] = v[r]; candI[off] = idx; off++; }
        }
        __syncwarp();
        float cv = FLT_MAX;
        int ci = 0x7FFFFFFF;
        if (lane < total) { cv = candV[lane]; ci = candI[lane]; }
        bitonic32(cv, ci, lane);
        if (lane < KK) outp[lane] = ci;
    } else {
        for (int k = 0; k < KK; k++) {
            float bv = v[0];
            int br = 0;
#pragma unroll
            for (int r = 1; r < 32; r++) {
                if (v[r] < bv) { bv = v[r]; br = r; }
            }
            int bi = lane + 32 * br;
#pragma unroll
            for (int o = 16; o > 0; o >>= 1) {
                float ov = __shfl_xor_sync(0xffffffffu, bv, o);
                int oi = __shfl_xor_sync(0xffffffffu, bi, o);
                if (ov < bv || (ov == bv && oi < bi)) { bv = ov; bi = oi; }
            }
            if (lane == 0) outp[k] = bi;
            if ((bi & 31) == lane) {
                int rr = bi >> 5;
#pragma unroll
                for (int r = 0; r < 32; r++)
                    if (r == rr) v[r] = FLT_MAX;
            }
        }
    }
}

// ---------------- kNN (D=1): sort-based window selection ------------------------
__global__ void __launch_bounds__(512) knn1_kernel(const float* __restrict__ x,
                                                   int* __restrict__ idx_out) {
    __shared__ float sv[NPTS];
    __shared__ int si[NPTS];
    const int b = blockIdx.x;
    const int tid = threadIdx.x;  // 512

    for (int t = tid; t < NPTS; t += 512) {
        sv[t] = x[(size_t)b * NPTS + t];
        si[t] = t;
    }
    __syncthreads();

    for (int size = 2; size <= NPTS; size <<= 1) {
        for (int stride = size >> 1; stride > 0; stride >>= 1) {
            int i = ((tid & ~(stride - 1)) << 1) | (tid & (stride - 1));
            int j = i | stride;
            float va = sv[i], vb = sv[j];
            int ia = si[i], ib = si[j];
            bool agtb = (va > vb) || (va == vb && ia > ib);
            bool asc = ((i & size) == 0);
            if (agtb == asc) { sv[i] = vb; si[i] = ib; sv[j] = va; si[j] = ia; }
            __syncthreads();
        }
    }

    const int w = tid >> 5, lane = tid & 31;
    for (int r = w * 64; r < w * 64 + 64; r++) {
        float xi = sv[r];
        int q = r - 15 + lane;
        bool valid = (q >= 0) && (q < NPTS);
        float cv = FLT_MAX;
        int ci = 0x7FFFFFFF;
        if (valid) {
            float xj = sv[q];
            cv = (xi * xi + xj * xj) - 2.f * (xi * xj);
            ci = si[q];
        }
        bitonic32(cv, ci, lane);
        int orig = si[r];
        if (lane < KK)
            idx_out[((size_t)(b * NPTS + orig)) * KK + lane] = ci;
    }
}

// ---------------- transpose: [NPTS, CH] -> [CH, NPTS] per batch ------------------
__global__ void __launch_bounds__(256) transpose_kernel(const float* __restrict__ feat,
                                                        float* __restrict__ featT) {
    __shared__ float tile[64 * 65];
    const int tid = threadIdx.x;
    const int bpB = NPTS / 64;
    const int b = blockIdx.x / bpB;
    const int row0 = (blockIdx.x % bpB) * 64;
    const float* fb = feat + ((size_t)b * NPTS + row0) * CH;
    for (int t = tid; t < 64 * 64; t += 256) {
        int r = t >> 6, c = t & 63;
        tile[c * 65 + r] = fb[r * CH + c];
    }
    __syncthreads();
    float* ob = featT + (size_t)b * CH * NPTS + row0;
    for (int t = tid; t < 64 * 64; t += 256) {
        int c = t >> 6, r = t & 63;
        ob[(size_t)c * NPTS + r] = tile[c * 65 + r];
    }
}

// ---------------- kNN (CH=64), FFMA2 paired over channel dimension --------------
// acc lanes hold even-c / odd-c partial sums; q pairs pre-staged in smem so each
// fma2 needs zero packing movs (v pairs need 4 movs per 36 fma2).
__global__ void __launch_bounds__(256) knn_t_kernel(const float* __restrict__ featT,
                                                    int* __restrict__ idx_out) {
    constexpr int PB = 8;
    __shared__ __align__(16) float dist[PB][NPTS];
    __shared__ __align__(16) float qp[(CH / 2) * 2 * PB];  // [cp][p][half]
    __shared__ float sqi[PB];

    const int tid = threadIdx.x;
    const int gbase = blockIdx.x * PB;
    const int b = gbase / NPTS;
    const int i0 = gbase % NPTS;
    const float* ftb = featT + (size_t)b * CH * NPTS;

    // qp[cp*16 + 2*p + half] = ftb[(2*cp+half)*NPTS + i0 + p]
    for (int t = tid; t < (CH / 2) * 2 * PB; t += 256) {
        int cp = t >> 4, r = t & 15;
        int p = r >> 1, half = r & 1;
        qp[t] = ftb[(size_t)(2 * cp + half) * NPTS + i0 + p];
    }
    __syncthreads();
    if (tid < PB) {
        float s = 0.f;
        for (int cp = 0; cp < CH / 2; cp++) {
            float q0 = qp[cp * 16 + 2 * tid];
            float q1 = qp[cp * 16 + 2 * tid + 1];
            s = fmaf(q0, q0, s);
            s = fmaf(q1, q1, s);
        }
        sqi[tid] = s;
    }
    __syncthreads();

    const float4* ft4 = (const float4*)ftb;
    ull acc[PB][4];  // [point][jj], lanes = (even-c partial, odd-c partial)
    ull sqp[4];
#pragma unroll
    for (int p = 0; p < PB; p++)
#pragma unroll
        for (int jj = 0; jj < 4; jj++) acc[p][jj] = 0ull;
#pragma unroll
    for (int jj = 0; jj < 4; jj++) sqp[jj] = 0ull;

    for (int cp = 0; cp < CH / 2; cp++) {
        float4 va = ft4[(2 * cp) * (NPTS / 4) + tid];
        float4 vb = ft4[(2 * cp + 1) * (NPTS / 4) + tid];
        ull v0 = pk(va.x, vb.x);
        ull v1 = pk(va.y, vb.y);
        ull v2 = pk(va.z, vb.z);
        ull v3 = pk(va.w, vb.w);
        fma2(sqp[0], v0, v0);
        fma2(sqp[1], v1, v1);
        fma2(sqp[2], v2, v2);
        fma2(sqp[3], v3, v3);
        const float* qb = &qp[cp * 16];
#pragma unroll
        for (int p = 0; p < PB; p++) {
            ull q = ld2(qb + 2 * p);
            fma2(acc[p][0], v0, q);
            fma2(acc[p][1], v1, q);
            fma2(acc[p][2], v2, q);
            fma2(acc[p][3], v3, q);
        }
    }
    float sqj[4];
#pragma unroll
    for (int jj = 0; jj < 4; jj++) {
        float2 s2 = upk(sqp[jj]);
        sqj[jj] = s2.x + s2.y;
    }
    const int j0 = tid * 4;
#pragma unroll
    for (int p = 0; p < PB; p++) {
        float4 dv;
        float2 d0 = upk(acc[p][0]);
        float2 d1 = upk(acc[p][1]);
        float2 d2 = upk(acc[p][2]);
        float2 d3 = upk(acc[p][3]);
        dv.x = sqi[p] + sqj[0] - 2.f * (d0.x + d0.y);
        dv.y = sqi[p] + sqj[1] - 2.f * (d1.x + d1.y);
        dv.z = sqi[p] + sqj[2] - 2.f * (d2.x + d2.y);
        dv.w = sqi[p] + sqj[3] - 2.f * (d3.x + d3.y);
        *(float4*)&dist[p][j0] = dv;
    }
    __syncthreads();

    const int g = tid >> 5, lane = tid & 31;
    warp_select16(dist[g], lane, &idx_out[((size_t)(b * NPTS + i0 + g)) * KK]);
}

// ---------------- Y/base precompute -------------------------------------------
template <int D>
__global__ void __launch_bounds__(256) yb_kernel(
    const float* __restrict__ feat, const float* __restrict__ w1,
    const float* __restrict__ b1, float* __restrict__ baseo,
    float* __restrict__ yo) {
    __shared__ float w1as[D * CH];
    __shared__ float w1bs[D * CH];
    __shared__ float b1s[CH];
    const int tid = threadIdx.x, p = tid >> 5, lane = tid & 31;
    for (int t = tid; t < D * CH; t += 256) {
        w1as[t] = w1[t];
        w1bs[t] = w1[D * CH + t];
    }
    if (tid < CH) b1s[tid] = b1[tid];
    __syncthreads();
    const int k0 = 2 * lane;
    for (int g = 0; g < 8; g++) {
        int i = blockIdx.x * 64 + g * 8 + p;
        const float* fx = feat + (size_t)i * D;
        float zx = 0.f, zy = 0.f, yx = 0.f, yy = 0.f;
        if constexpr (D == 1) {
            float xv = fx[0];
            float2 wa = *(const float2*)&w1as[k0];
            float2 wb = *(const float2*)&w1bs[k0];
            zx = xv * wa.x; zy = xv * wa.y;
            yx = xv * wb.x; yy = xv * wb.y;
        } else {
            float xr[D / 32];
#pragma unroll
            for (int h = 0; h < D / 32; h++) xr[h] = fx[h * 32 + lane];
#pragma unroll
            for (int h = 0; h < D / 32; h++) {
                for (int j = 0; j < 32; j++) {
                    float xv = __shfl_sync(0xffffffffu, xr[h], j);
                    float2 wa = *(const float2*)&w1as[(h * 32 + j) * CH + k0];
                    float2 wb = *(const float2*)&w1bs[(h * 32 + j) * CH + k0];
                    zx = fmaf(xv, wa.x, zx); zy = fmaf(xv, wa.y, zy);
                    yx = fmaf(xv, wb.x, yx); yy = fmaf(xv, wb.y, yy);
                }
            }
        }
        *(float2*)&baseo[(size_t)i * CH + k0] =
            make_float2(b1s[k0] + zx - yx, b1s[k0 + 1] + zy - yy);
        *(float2*)&yo[(size_t)i * CH + k0] = make_float2(yx, yy);
    }
}

// ---------------- EdgeConv: h1 = relu(base_i + Y_j); out = max_k h1@w2 + b2 -----
// Stage-2 uses FFMA2 paired over j: w2 pre-packed interleaved in smem so both
// fma2 operands are natural 64-bit pairs (zero packing movs).
__global__ void __launch_bounds__(256, 4) edgeconv_kernel(
    const int* __restrict__ idx, const float* __restrict__ basep,
    const float* __restrict__ yp, const float* __restrict__ w2,
    const float* __restrict__ b2, float* __restrict__ out) {
    constexpr int PTS = 8;
    constexpr int NB = 8;
    constexpr int GROUPS = 4;
    extern __shared__ float s[];
    float* w2p = s;                           // CH/2 x CH x 2 interleaved
    float* b2s = w2p + CH * CH;
    float* ys  = b2s + CH;
    int* nbr   = (int*)(ys + PTS * NB * CH);

    const int tid = threadIdx.x;
    const int p = tid >> 5, lane = tid & 31;

    // w2p[(j/2)*128 + 2*c + (j&1)] = w2[j*CH + c]
    for (int t = tid; t < CH * CH; t += 256) {
        int j = t >> 6, c = t & 63;
        w2p[(j >> 1) * (2 * CH) + 2 * c + (j & 1)] = w2[t];
    }
    if (tid < CH) b2s[tid] = b2[tid];
    __syncthreads();

    const int k0 = 2 * lane;

    for (int grp = 0; grp < GROUPS; grp++) {
        const int gbase = blockIdx.x * (PTS * GROUPS) + grp * PTS;
        const int b = gbase / NPTS;
        const int i = (gbase % NPTS) + p;
        const int gi = b * NPTS + i;
        const float* yb = yp + (size_t)b * NPTS * CH;

        if (lane < KK) nbr[p * KK + lane] = idx[(size_t)gi * KK + lane];
        __syncwarp();

        float2 bse = *(const float2*)&basep[(size_t)gi * CH + k0];
        float bx = bse.x, by = bse.y;
        float mx = -FLT_MAX, my = -FLT_MAX;

        for (int c0 = 0; c0 < KK; c0 += NB) {
            for (int t = lane; t < NB * (CH / 4); t += 32) {
                int nb = t >> 4, c4 = t & 15;
                float4 vv = *(const float4*)(yb +
                    (size_t)nbr[p * KK + c0 + nb] * CH + 4 * c4);
                *(float4*)&ys[(p * NB + nb) * CH + 4 * c4] = vv;
            }
            __syncwarp();

#pragma unroll
            for (int nb = 0; nb < NB; nb++) {
                float2 h = *(const float2*)&ys[(p * NB + nb) * CH + k0];
                h.x = fmaxf(bx + h.x, 0.f);
                h.y = fmaxf(by + h.y, 0.f);
                *(float2*)&ys[(p * NB + nb) * CH + k0] = h;
            }
            __syncwarp();

            // stage 2: acc lanes hold (even-j, odd-j) partial sums
            ull acc2[NB][2];
#pragma unroll
            for (int nb = 0; nb < NB; nb++) { acc2[nb][0] = 0ull; acc2[nb][1] = 0ull; }
            const float* hbase = &ys[p * NB * CH];
            for (int jp = 0; jp < CH / 2; jp += 2) {
                const float* wb = &w2p[jp * (2 * CH) + 2 * k0];
                ull w00 = ld2(wb);                 // jp,   ch k0
                ull w01 = ld2(wb + 2);             // jp,   ch k0+1
                ull w10 = ld2(wb + 2 * CH);        // jp+1, ch k0
                ull w11 = ld2(wb + 2 * CH + 2);    // jp+1, ch k0+1
#pragma unroll
                for (int nb = 0; nb < NB; nb++) {
                    float4 h4 = *(const float4*)(hbase + nb * CH + 2 * jp);
                    ull h0, h1;
                    memcpy(&h0, &h4.x, 8);
                    memcpy(&h1, &h4.z, 8);
                    fma2(acc2[nb][0], h0, w00);
                    fma2(acc2[nb][1], h0, w01);
                    fma2(acc2[nb][0], h1, w10);
                    fma2(acc2[nb][1], h1, w11);
                }
            }
#pragma unroll
            for (int nb = 0; nb < NB; nb++) {
                float2 a0 = upk(acc2[nb][0]);
                float2 a1 = upk(acc2[nb][1]);
                mx = fmaxf(mx, a0.x + a0.y);
                my = fmaxf(my, a1.x + a1.y);
            }
            __syncwarp();
        }

        size_t ob = (size_t)gi * CH;
        out[ob + k0]     = mx + b2s[k0];
        out[ob + k0 + 1] = my + b2s[k0 + 1];
    }
}

// ---------------- final MLP: 192 -> 128 -> 64 -> 32 -> 2, log_softmax ------------
// Layers 1-2 use j-paired FFMA2 with interleaved pre-packed weights.
__global__ void __launch_bounds__(512) mlp_kernel(
    const float* __restrict__ x1, const float* __restrict__ x2,
    const float* __restrict__ x3,
    const float* __restrict__ mw1, const float* __restrict__ mb1,
    const float* __restrict__ mw2, const float* __restrict__ mb2,
    const float* __restrict__ mw3, const float* __restrict__ mb3,
    const float* __restrict__ mw4, const float* __restrict__ mb4,
    float* __restrict__ out) {
    extern __shared__ float s[];
    float* w1p = s;               // 96 x 128 x 2 interleaved = 24576
    float* w2p = w1p + 24576;     // 64 x 64 x 2 interleaved = 8192
    float* w3s = w2p + 8192;
    float* w4s = w3s + 2048;
    float* b1s = w4s + 64;
    float* b2s = b1s + 128;
    float* b3s = b2s + 64;
    float* b4s = b3s + 32;
    float* fbuf = b4s + 4;
    float* hbuf = fbuf + 16 * 192;

    const int tid = threadIdx.x;
    const int w = tid >> 5, lane = tid & 31;
    // w1p[(j/2)*256 + 2*c + (j&1)] = mw1[j*128 + c]
    for (int t = tid; t < 24576; t += 512) {
        int j = t >> 7, c = t & 127;
        w1p[(j >> 1) * 256 + 2 * c + (j & 1)] = mw1[t];
    }
    // w2p[(j/2)*128 + 2*c + (j&1)] = mw2[j*64 + c]
    for (int t = tid; t < 8192; t += 512) {
        int j = t >> 6, c = t & 63;
        w2p[(j >> 1) * 128 + 2 * c + (j & 1)] = mw2[t];
    }
    for (int t = tid; t < 2048; t += 512) w3s[t] = mw3[t];
    if (tid < 64) w4s[tid] = mw4[tid];
    if (tid < 128) b1s[tid] = mb1[tid];
    if (tid < 64) b2s[tid] = mb2[tid];
    if (tid < 32) b3s[tid] = mb3[tid];
    if (tid < 2) b4s[tid] = mb4[tid];
    __syncthreads();

    const int total = BATCH * NPTS;
    const int ptsPerBlock = (total + gridDim.x - 1) / gridDim.x;
    const int pbase = blockIdx.x * ptsPerBlock;
    const int pend = min(pbase + ptsPerBlock, total);
    float* f = fbuf + w * 192;
    float* h = hbuf + w * 128;

    for (int pt = pbase + w; pt < pend; pt += 16) {
        for (int t = lane; t < 64; t += 32) {
            f[t]       = x1[(size_t)pt * 64 + t];
            f[64 + t]  = x2[(size_t)pt * 64 + t];
            f[128 + t] = x3[(size_t)pt * 64 + t];
        }
        __syncwarp();
        // layer 1: 192 -> 128, lane owns 4 channels; pairs over j
        ull a1[4];
#pragma unroll
        for (int cc = 0; cc < 4; cc++) a1[cc] = 0ull;
        const int c0 = 4 * lane;
        for (int jp = 0; jp < 96; jp++) {
            ull xp = ld2(&f[2 * jp]);
            const float* wb = &w1p[jp * 256 + 2 * c0];
            fma2(a1[0], xp, ld2(wb));
            fma2(a1[1], xp, ld2(wb + 2));
            fma2(a1[2], xp, ld2(wb + 4));
            fma2(a1[3], xp, ld2(wb + 6));
        }
#pragma unroll
        for (int cc = 0; cc < 4; cc++) {
            float2 a = upk(a1[cc]);
            h[c0 + cc] = fmaxf(b1s[c0 + cc] + a.x + a.y, 0.f);
        }
        __syncwarp();
        // layer 2: 128 -> 64, lane owns 2 channels; pairs over j
        ull a2[2];
        a2[0] = 0ull; a2[1] = 0ull;
        const int d0 = 2 * lane;
        for (int jp = 0; jp < 64; jp++) {
            ull hp = ld2(&h[2 * jp]);
            const float* wb = &w2p[jp * 128 + 2 * d0];
            fma2(a2[0], hp, ld2(wb));
            fma2(a2[1], hp, ld2(wb + 2));
        }
        __syncwarp();
        {
            float2 a0 = upk(a2[0]);
            float2 a1v = upk(a2[1]);
            f[d0]     = fmaxf(b2s[d0] + a0.x + a0.y, 0.f);
            f[d0 + 1] = fmaxf(b2s[d0 + 1] + a1v.x + a1v.y, 0.f);
        }
        __syncwarp();
        // layer 3: 64 -> 32
        float a3 = b3s[lane];
        for (int j = 0; j < 64; j++) a3 = fmaf(f[j], w3s[j * 32 + lane], a3);
        a3 = fmaxf(a3, 0.f);
        __syncwarp();
        h[lane] = a3;
        __syncwarp();
        // layer 4 + log_softmax (2 classes)
        float o = 0.f;
        if (lane < 2) {
            o = b4s[lane];
            for (int j = 0; j < 32; j++) o = fmaf(h[j], w4s[j * 2 + lane], o);
        }
        float oo = __shfl_xor_sync(0xffffffffu, o, 1);
        if (lane < 2) {
            float mm = fmaxf(o, oo);
            float lse = mm + logf(expf(o - mm) + expf(oo - mm));
            out[(size_t)pt * 2 + lane] = o - lse;
        }
        __syncwarp();
    }
}

// ---------------- launch -------------------------------------------------------
static constexpr size_t EC_SMEM =
    (size_t)(CH * CH + CH + 8 * 8 * CH) * 4 + 8 * KK * 4;
static constexpr size_t MLP_SMEM =
    (size_t)(24576 + 8192 + 2048 + 64 + 128 + 64 + 32 + 4 + 16 * 192 + 16 * 128) * 4;

extern "C" void kernel_launch(void* const* d_in, const int* in_sizes, int n_in,
                              void* d_out, int out_size) {
    (void)in_sizes; (void)n_in; (void)out_size;
    const float* x    = (const float*)d_in[0];
    const float* c1w1 = (const float*)d_in[1];
    const float* c1b1 = (const float*)d_in[2];
    const float* c1w2 = (const float*)d_in[3];
    const float* c1b2 = (const float*)d_in[4];
    const float* c2w1 = (const float*)d_in[5];
    const float* c2b1 = (const float*)d_in[6];
    const float* c2w2 = (const float*)d_in[7];
    const float* c2b2 = (const float*)d_in[8];
    const float* c3w1 = (const float*)d_in[9];
    const float* c3b1 = (const float*)d_in[10];
    const float* c3w2 = (const float*)d_in[11];
    const float* c3b2 = (const float*)d_in[12];
    const float* mw1  = (const float*)d_in[13];
    const float* mb1  = (const float*)d_in[14];
    const float* mw2  = (const float*)d_in[15];
    const float* mb2  = (const float*)d_in[16];
    const float* mw3  = (const float*)d_in[17];
    const float* mb3  = (const float*)d_in[18];
    const float* mw4  = (const float*)d_in[19];
    const float* mb4  = (const float*)d_in[20];
    float* outp = (float*)d_out;

    float *x1p, *x2p, *x3p, *xtp, *basep, *yp;
    int* idxp;
    cudaGetSymbolAddress((void**)&x1p, g_x1);
    cudaGetSymbolAddress((void**)&x2p, g_x2);
    cudaGetSymbolAddress((void**)&x3p, g_x3);
    cudaGetSymbolAddress((void**)&xtp, g_xt);
    cudaGetSymbolAddress((void**)&basep, g_base);
    cudaGetSymbolAddress((void**)&yp, g_y);
    cudaGetSymbolAddress((void**)&idxp, g_idx);

    cudaFuncSetAttribute(edgeconv_kernel,
                         cudaFuncAttributeMaxDynamicSharedMemorySize, (int)EC_SMEM);
    cudaFuncSetAttribute(mlp_kernel,
                         cudaFuncAttributeMaxDynamicSharedMemorySize, (int)MLP_SMEM);

    const int nblk_knn  = BATCH * NPTS / 8;   // 8192
    const int nblk_ec   = BATCH * NPTS / 32;  // 2048
    const int nblk_yb   = BATCH * NPTS / 64;  // 1024
    const int nblk_tr   = BATCH * (NPTS / 64);// 1024

    knn1_kernel<<<BATCH, 512>>>(x, idxp);
    yb_kernel<1><<<nblk_yb, 256>>>(x, c1w1, c1b1, basep, yp);
    edgeconv_kernel<<<nblk_ec, 256, EC_SMEM>>>(idxp, basep, yp, c1w2, c1b2, x1p);

    transpose_kernel<<<nblk_tr, 256>>>(x1p, xtp);
    knn_t_kernel<<<nblk_knn, 256>>>(xtp, idxp);
    yb_kernel<64><<<nblk_yb, 256>>>(x1p, c2w1, c2b1, basep, yp);
    edgeconv_kernel<<<nblk_ec, 256, EC_SMEM>>>(idxp, basep, yp, c2w2, c2b2, x2p);

    transpose_kernel<<<nblk_tr, 256>>>(x2p, xtp);
    knn_t_kernel<<<nblk_knn, 256>>>(xtp, idxp);
    yb_kernel<64><<<nblk_yb, 256>>>(x2p, c3w1, c3b1, basep, yp);
    edgeconv_kernel<<<nblk_ec, 256, EC_SMEM>>>(idxp, basep, yp, c3w2, c3b2, x3p);

    mlp_kernel<<<148, 512, MLP_SMEM>>>(x1p, x2p, x3p, mw1, mb1, mw2, mb2,
                                       mw3, mb3, mw4, mb4, outp);
}

// round 13
// speedup vs baseline: 1.2600x; 1.2600x over previous
#include <cuda_runtime.h>
#include <math.h>
#include <float.h>
#include <string.h>

#define BATCH 64
#define NPTS  1024
#define KK    16
#define CH    64

typedef unsigned long long ull;

// ---------------- packed f32x2 helpers (kept where R11 measured OK) -------------
__device__ __forceinline__ ull pk2(float x) {
    ull r;
    asm("mov.b64 %0, {%1, %1};" : "=l"(r) : "f"(x));
    return r;
}
__device__ __forceinline__ void fma2(ull& d, ull a, ull b) {
    asm("fma.rn.f32x2 %0, %1, %2, %0;" : "+l"(d) : "l"(a), "l"(b));
}
__device__ __forceinline__ float2 upk(ull v) {
    float2 r;
    asm("mov.b64 {%0, %1}, %2;" : "=f"(r.x), "=f"(r.y) : "l"(v));
    return r;
}
__device__ __forceinline__ ull ld2(const float* p) {
    ull r;
    memcpy(&r, p, 8);
    return r;
}

// ---------------- scratch (static device globals; no allocation) ----------------
__device__ __align__(16) float g_x1[BATCH * NPTS * CH];
__device__ __align__(16) float g_x2[BATCH * NPTS * CH];
__device__ __align__(16) float g_x3[BATCH * NPTS * CH];
__device__ __align__(16) float g_xt[BATCH * NPTS * CH];   // transposed features
__device__ __align__(16) float g_base[BATCH * NPTS * CH]; // b1 + x@w1a - x@w1b
__device__ __align__(16) float g_y[BATCH * NPTS * CH];    // x@w1b
__device__ int g_idx[BATCH * NPTS * KK];

// ---------------- warp bitonic sort of 32 (value,index) pairs, lex ascending ----
__device__ __forceinline__ void bitonic32(float& sv, int& si, int lane) {
#pragma unroll
    for (int size = 2; size <= 32; size <<= 1) {
#pragma unroll
        for (int stride = size >> 1; stride > 0; stride >>= 1) {
            float ov = __shfl_xor_sync(0xffffffffu, sv, stride);
            int oi = __shfl_xor_sync(0xffffffffu, si, stride);
            bool dirDesc = (lane & size) != 0;
            bool iAmLower = (lane & stride) == 0;
            bool wantSmaller = iAmLower != dirDesc;
            bool otherLess = (ov < sv) || (ov == sv && oi < si);
            if (wantSmaller == otherLess) { sv = ov; si = oi; }
        }
    }
}

// ---------------- warp top-16 selection from a 1024 row (exact lex) -------------
__device__ __forceinline__ void warp_select16(float* row, int lane,
                                              int* __restrict__ outp) {
    float v[32];
#pragma unroll
    for (int r = 0; r < 32; r++) v[r] = row[lane + 32 * r];

    float lv = v[0];
    int li = lane;
#pragma unroll
    for (int r = 1; r < 32; r++) {
        if (v[r] < lv) { lv = v[r]; li = lane + 32 * r; }
    }
    float sv = lv; int si = li;
    bitonic32(sv, si, lane);
    float Tv = __shfl_sync(0xffffffffu, sv, 15);
    int   Ti = __shfl_sync(0xffffffffu, si, 15);

    int cnt = 0;
#pragma unroll
    for (int r = 0; r < 32; r++) {
        int idx = lane + 32 * r;
        bool le = (v[r] < Tv) || (v[r] == Tv && idx <= Ti);
        cnt += le ? 1 : 0;
    }
    int total = __reduce_add_sync(0xffffffffu, cnt);

    if (total <= 32) {
        int pre = cnt;
#pragma unroll
        for (int o = 1; o < 32; o <<= 1) {
            int n = __shfl_up_sync(0xffffffffu, pre, o);
            if (lane >= o) pre += n;
        }
        pre -= cnt;
        float* candV = row;
        int* candI = (int*)(row + 32);
        int off = pre;
#pragma unroll
        for (int r = 0; r < 32; r++) {
            int idx = lane + 32 * r;
            bool le = (v[r] < Tv) || (v[r] == Tv && idx <= Ti);
            if (le) { candV[off] = v[r]; candI[off] = idx; off++; }
        }
        __syncwarp();
        float cv = FLT_MAX;
        int ci = 0x7FFFFFFF;
        if (lane < total) { cv = candV[lane]; ci = candI[lane]; }
        bitonic32(cv, ci, lane);
        if (lane < KK) outp[lane] = ci;
    } else {
        for (int k = 0; k < KK; k++) {
            float bv = v[0];
            int br = 0;
#pragma unroll
            for (int r = 1; r < 32; r++) {
                if (v[r] < bv) { bv = v[r]; br = r; }
            }
            int bi = lane + 32 * br;
#pragma unroll
            for (int o = 16; o > 0; o >>= 1) {
                float ov = __shfl_xor_sync(0xffffffffu, bv, o);
                int oi = __shfl_xor_sync(0xffffffffu, bi, o);
                if (ov < bv || (ov == bv && oi < bi)) { bv = ov; bi = oi; }
            }
            if (lane == 0) outp[k] = bi;
            if ((bi & 31) == lane) {
                int rr = bi >> 5;
#pragma unroll
                for (int r = 0; r < 32; r++)
                    if (r == rr) v[r] = FLT_MAX;
            }
        }
    }
}

// ---------------- kNN (D=1): sort-based window selection ------------------------
__global__ void __launch_bounds__(512) knn1_kernel(const float* __restrict__ x,
                                                   int* __restrict__ idx_out) {
    __shared__ float sv[NPTS];
    __shared__ int si[NPTS];
    const int b = blockIdx.x;
    const int tid = threadIdx.x;  // 512

    for (int t = tid; t < NPTS; t += 512) {
        sv[t] = x[(size_t)b * NPTS + t];
        si[t] = t;
    }
    __syncthreads();

    for (int size = 2; size <= NPTS; size <<= 1) {
        for (int stride = size >> 1; stride > 0; stride >>= 1) {
            int i = ((tid & ~(stride - 1)) << 1) | (tid & (stride - 1));
            int j = i | stride;
            float va = sv[i], vb = sv[j];
            int ia = si[i], ib = si[j];
            bool agtb = (va > vb) || (va == vb && ia > ib);
            bool asc = ((i & size) == 0);
            if (agtb == asc) { sv[i] = vb; si[i] = ib; sv[j] = va; si[j] = ia; }
            __syncthreads();
        }
    }

    const int w = tid >> 5, lane = tid & 31;
    for (int r = w * 64; r < w * 64 + 64; r++) {
        float xi = sv[r];
        int q = r - 15 + lane;
        bool valid = (q >= 0) && (q < NPTS);
        float cv = FLT_MAX;
        int ci = 0x7FFFFFFF;
        if (valid) {
            float xj = sv[q];
            cv = (xi * xi + xj * xj) - 2.f * (xi * xj);
            ci = si[q];
        }
        bitonic32(cv, ci, lane);
        int orig = si[r];
        if (lane < KK)
            idx_out[((size_t)(b * NPTS + orig)) * KK + lane] = ci;
    }
}

// ---------------- transpose: [NPTS, CH] -> [CH, NPTS] per batch ------------------
__global__ void __launch_bounds__(256) transpose_kernel(const float* __restrict__ feat,
                                                        float* __restrict__ featT) {
    __shared__ float tile[64 * 65];
    const int tid = threadIdx.x;
    const int bpB = NPTS / 64;
    const int b = blockIdx.x / bpB;
    const int row0 = (blockIdx.x % bpB) * 64;
    const float* fb = feat + ((size_t)b * NPTS + row0) * CH;
    for (int t = tid; t < 64 * 64; t += 256) {
        int r = t >> 6, c = t & 63;
        tile[c * 65 + r] = fb[r * CH + c];
    }
    __syncthreads();
    float* ob = featT + (size_t)b * CH * NPTS + row0;
    for (int t = tid; t < 64 * 64; t += 256) {
        int c = t >> 6, r = t & 63;
        ob[(size_t)c * NPTS + r] = tile[c * 65 + r];
    }
}

// ---------------- kNN (CH=64): PB=16 queries/block (halved L2 traffic) ----------
__global__ void __launch_bounds__(256, 2) knn_t_kernel(const float* __restrict__ featT,
                                                       int* __restrict__ idx_out) {
    constexpr int PB = 16;
    __shared__ __align__(16) float dist[PB][NPTS];  // 64 KB
    __shared__ __align__(16) float xqT[CH * PB];    // [c][p], 4 KB
    __shared__ float sqi[PB];

    const int tid = threadIdx.x;
    const int gbase = blockIdx.x * PB;
    const int b = gbase / NPTS;
    const int i0 = gbase % NPTS;
    const float* ftb = featT + (size_t)b * CH * NPTS;

    // stage the 16 query columns: xqT[c*16+p] = ftb[c*NPTS + i0+p]
    for (int t = tid; t < CH * PB; t += 256) {
        int c = t >> 4, p = t & 15;
        xqT[t] = ftb[(size_t)c * NPTS + i0 + p];
    }
    __syncthreads();
    if (tid < PB) {
        float s = 0.f;
        for (int c = 0; c < CH; c++) { float q = xqT[c * 16 + tid]; s = fmaf(q, q, s); }
        sqi[tid] = s;
    }
    __syncthreads();

    // distance: thread owns 4 consecutive j (coalesced float4 across lanes)
    const float4* ft4 = (const float4*)ftb;
    float dot[PB][4];
    float sqj[4];
#pragma unroll
    for (int p = 0; p < PB; p++)
#pragma unroll
        for (int jj = 0; jj < 4; jj++) dot[p][jj] = 0.f;
#pragma unroll
    for (int jj = 0; jj < 4; jj++) sqj[jj] = 0.f;

    for (int c = 0; c < CH; c++) {
        float4 v = ft4[c * (NPTS / 4) + tid];
        sqj[0] = fmaf(v.x, v.x, sqj[0]);
        sqj[1] = fmaf(v.y, v.y, sqj[1]);
        sqj[2] = fmaf(v.z, v.z, sqj[2]);
        sqj[3] = fmaf(v.w, v.w, sqj[3]);
        const float* qb = &xqT[c * 16];
        float4 q0 = *(const float4*)(qb);
        float4 q1 = *(const float4*)(qb + 4);
        float4 q2 = *(const float4*)(qb + 8);
        float4 q3 = *(const float4*)(qb + 12);
        float q[16] = {q0.x, q0.y, q0.z, q0.w, q1.x, q1.y, q1.z, q1.w,
                       q2.x, q2.y, q2.z, q2.w, q3.x, q3.y, q3.z, q3.w};
#pragma unroll
        for (int p = 0; p < PB; p++) {
            dot[p][0] = fmaf(v.x, q[p], dot[p][0]);
            dot[p][1] = fmaf(v.y, q[p], dot[p][1]);
            dot[p][2] = fmaf(v.z, q[p], dot[p][2]);
            dot[p][3] = fmaf(v.w, q[p], dot[p][3]);
        }
    }
    const int j0 = tid * 4;
#pragma unroll
    for (int p = 0; p < PB; p++) {
        float4 dv;
        dv.x = sqi[p] + sqj[0] - 2.f * dot[p][0];
        dv.y = sqi[p] + sqj[1] - 2.f * dot[p][1];
        dv.z = sqi[p] + sqj[2] - 2.f * dot[p][2];
        dv.w = sqi[p] + sqj[3] - 2.f * dot[p][3];
        *(float4*)&dist[p][j0] = dv;
    }
    __syncthreads();

    // selection: 8 warps x 2 rows each
    const int g = tid >> 5, lane = tid & 31;
    warp_select16(dist[2 * g], lane,
                  &idx_out[((size_t)(b * NPTS + i0 + 2 * g)) * KK]);
    warp_select16(dist[2 * g + 1], lane,
                  &idx_out[((size_t)(b * NPTS + i0 + 2 * g + 1)) * KK]);
}

// ---------------- Y/base precompute -------------------------------------------
template <int D>
__global__ void __launch_bounds__(256) yb_kernel(
    const float* __restrict__ feat, const float* __restrict__ w1,
    const float* __restrict__ b1, float* __restrict__ baseo,
    float* __restrict__ yo) {
    __shared__ float w1as[D * CH];
    __shared__ float w1bs[D * CH];
    __shared__ float b1s[CH];
    const int tid = threadIdx.x, p = tid >> 5, lane = tid & 31;
    for (int t = tid; t < D * CH; t += 256) {
        w1as[t] = w1[t];
        w1bs[t] = w1[D * CH + t];
    }
    if (tid < CH) b1s[tid] = b1[tid];
    __syncthreads();
    const int k0 = 2 * lane;
    for (int g = 0; g < 8; g++) {
        int i = blockIdx.x * 64 + g * 8 + p;
        const float* fx = feat + (size_t)i * D;
        float zx = 0.f, zy = 0.f, yx = 0.f, yy = 0.f;
        if constexpr (D == 1) {
            float xv = fx[0];
            float2 wa = *(const float2*)&w1as[k0];
            float2 wb = *(const float2*)&w1bs[k0];
            zx = xv * wa.x; zy = xv * wa.y;
            yx = xv * wb.x; yy = xv * wb.y;
        } else {
            float xr[D / 32];
#pragma unroll
            for (int h = 0; h < D / 32; h++) xr[h] = fx[h * 32 + lane];
#pragma unroll
            for (int h = 0; h < D / 32; h++) {
                for (int j = 0; j < 32; j++) {
                    float xv = __shfl_sync(0xffffffffu, xr[h], j);
                    float2 wa = *(const float2*)&w1as[(h * 32 + j) * CH + k0];
                    float2 wb = *(const float2*)&w1bs[(h * 32 + j) * CH + k0];
                    zx = fmaf(xv, wa.x, zx); zy = fmaf(xv, wa.y, zy);
                    yx = fmaf(xv, wb.x, yx); yy = fmaf(xv, wb.y, yy);
                }
            }
        }
        *(float2*)&baseo[(size_t)i * CH + k0] =
            make_float2(b1s[k0] + zx - yx, b1s[k0 + 1] + zy - yy);
        *(float2*)&yo[(size_t)i * CH + k0] = make_float2(yx, yy);
    }
}

// ---------------- EdgeConv: h1 = relu(base_i + Y_j); out = max_k h1@w2 + b2 -----
// (R11 form: FFMA2 stage-2 with channel-pair acc; measured best)
__global__ void __launch_bounds__(256, 4) edgeconv_kernel(
    const int* __restrict__ idx, const float* __restrict__ basep,
    const float* __restrict__ yp, const float* __restrict__ w2,
    const float* __restrict__ b2, float* __restrict__ out) {
    constexpr int PTS = 8;
    constexpr int NB = 8;
    constexpr int GROUPS = 4;
    extern __shared__ float s[];
    float* w2s = s;
    float* b2s = w2s + CH * CH;
    float* ys  = b2s + CH;
    int* nbr   = (int*)(ys + PTS * NB * CH);

    const int tid = threadIdx.x;
    const int p = tid >> 5, lane = tid & 31;

    for (int t = tid; t < CH * CH; t += 256) w2s[t] = w2[t];
    if (tid < CH) b2s[tid] = b2[tid];
    __syncthreads();

    const int k0 = 2 * lane;

    for (int grp = 0; grp < GROUPS; grp++) {
        const int gbase = blockIdx.x * (PTS * GROUPS) + grp * PTS;
        const int b = gbase / NPTS;
        const int i = (gbase % NPTS) + p;
        const int gi = b * NPTS + i;
        const float* yb = yp + (size_t)b * NPTS * CH;

        if (lane < KK) nbr[p * KK + lane] = idx[(size_t)gi * KK + lane];
        __syncwarp();

        float2 bse = *(const float2*)&basep[(size_t)gi * CH + k0];
        float bx = bse.x, by = bse.y;
        float mx = -FLT_MAX, my = -FLT_MAX;

        for (int c0 = 0; c0 < KK; c0 += NB) {
            for (int t = lane; t < NB * (CH / 4); t += 32) {
                int nb = t >> 4, c4 = t & 15;
                float4 vv = *(const float4*)(yb +
                    (size_t)nbr[p * KK + c0 + nb] * CH + 4 * c4);
                *(float4*)&ys[(p * NB + nb) * CH + 4 * c4] = vv;
            }
            __syncwarp();

#pragma unroll
            for (int nb = 0; nb < NB; nb++) {
                float2 h = *(const float2*)&ys[(p * NB + nb) * CH + k0];
                h.x = fmaxf(bx + h.x, 0.f);
                h.y = fmaxf(by + h.y, 0.f);
                *(float2*)&ys[(p * NB + nb) * CH + k0] = h;
            }
            __syncwarp();

            ull acc2[NB];
#pragma unroll
            for (int nb = 0; nb < NB; nb++) acc2[nb] = 0ull;
            const float* hbase = &ys[p * NB * CH];
            for (int j = 0; j < CH; j += 4) {
                const float* wb = &w2s[j * CH + k0];
                ull w0 = ld2(wb);
                ull w1 = ld2(wb + CH);
                ull w2v = ld2(wb + 2 * CH);
                ull w3v = ld2(wb + 3 * CH);
#pragma unroll
                for (int nb = 0; nb < NB; nb++) {
                    float4 hv = *(const float4*)(hbase + nb * CH + j);
                    fma2(acc2[nb], pk2(hv.x), w0);
                    fma2(acc2[nb], pk2(hv.y), w1);
                    fma2(acc2[nb], pk2(hv.z), w2v);
                    fma2(acc2[nb], pk2(hv.w), w3v);
                }
            }
#pragma unroll
            for (int nb = 0; nb < NB; nb++) {
                float2 a = upk(acc2[nb]);
                mx = fmaxf(mx, a.x);
                my = fmaxf(my, a.y);
            }
            __syncwarp();
        }

        size_t ob = (size_t)gi * CH;
        out[ob + k0]     = mx + b2s[k0];
        out[ob + k0 + 1] = my + b2s[k0 + 1];
    }
}

// ---------------- final MLP: 192 -> 128 -> 64 -> 32 -> 2, log_softmax ------------
__global__ void __launch_bounds__(512) mlp_kernel(
    const float* __restrict__ x1, const float* __restrict__ x2,
    const float* __restrict__ x3,
    const float* __restrict__ mw1, const float* __restrict__ mb1,
    const float* __restrict__ mw2, const float* __restrict__ mb2,
    const float* __restrict__ mw3, const float* __restrict__ mb3,
    const float* __restrict__ mw4, const float* __restrict__ mb4,
    float* __restrict__ out) {
    extern __shared__ float s[];
    float* w1s = s;
    float* w2s = w1s + 24576;
    float* w3s = w2s + 8192;
    float* w4s = w3s + 2048;
    float* b1s = w4s + 64;
    float* b2s = b1s + 128;
    float* b3s = b2s + 64;
    float* b4s = b3s + 32;
    float* fbuf = b4s + 4;
    float* hbuf = fbuf + 16 * 192;

    const int tid = threadIdx.x;
    const int w = tid >> 5, lane = tid & 31;
    for (int t = tid; t < 24576; t += 512) w1s[t] = mw1[t];
    for (int t = tid; t < 8192; t += 512) w2s[t] = mw2[t];
    for (int t = tid; t < 2048; t += 512) w3s[t] = mw3[t];
    if (tid < 64) w4s[tid] = mw4[tid];
    if (tid < 128) b1s[tid] = mb1[tid];
    if (tid < 64) b2s[tid] = mb2[tid];
    if (tid < 32) b3s[tid] = mb3[tid];
    if (tid < 2) b4s[tid] = mb4[tid];
    __syncthreads();

    const int total = BATCH * NPTS;
    const int ptsPerBlock = (total + gridDim.x - 1) / gridDim.x;
    const int pbase = blockIdx.x * ptsPerBlock;
    const int pend = min(pbase + ptsPerBlock, total);
    float* f = fbuf + w * 192;
    float* h = hbuf + w * 128;

    for (int pt = pbase + w; pt < pend; pt += 16) {
        for (int t = lane; t < 64; t += 32) {
            f[t]       = x1[(size_t)pt * 64 + t];
            f[64 + t]  = x2[(size_t)pt * 64 + t];
            f[128 + t] = x3[(size_t)pt * 64 + t];
        }
        __syncwarp();
        // layer 1: 192 -> 128, lane owns 4 channels (2 packed pairs)
        ull a1lo = ld2(&b1s[4 * lane]);
        ull a1hi = ld2(&b1s[4 * lane + 2]);
        for (int j = 0; j < 192; j += 4) {
            float4 xv = *(const float4*)&f[j];
            const float* wb = &w1s[j * 128 + 4 * lane];
            float4 w0 = *(const float4*)(wb);
            float4 w1v = *(const float4*)(wb + 128);
            float4 w2v = *(const float4*)(wb + 256);
            float4 w3v = *(const float4*)(wb + 384);
            ull xx;
            xx = pk2(xv.x);
            { ull wl, wh; memcpy(&wl, &w0.x, 8); memcpy(&wh, &w0.z, 8);
              fma2(a1lo, xx, wl); fma2(a1hi, xx, wh); }
            xx = pk2(xv.y);
            { ull wl, wh; memcpy(&wl, &w1v.x, 8); memcpy(&wh, &w1v.z, 8);
              fma2(a1lo, xx, wl); fma2(a1hi, xx, wh); }
            xx = pk2(xv.z);
            { ull wl, wh; memcpy(&wl, &w2v.x, 8); memcpy(&wh, &w2v.z, 8);
              fma2(a1lo, xx, wl); fma2(a1hi, xx, wh); }
            xx = pk2(xv.w);
            { ull wl, wh; memcpy(&wl, &w3v.x, 8); memcpy(&wh, &w3v.z, 8);
              fma2(a1lo, xx, wl); fma2(a1hi, xx, wh); }
        }
        {
            float2 alo = upk(a1lo), ahi = upk(a1hi);
            h[4 * lane]     = fmaxf(alo.x, 0.f);
            h[4 * lane + 1] = fmaxf(alo.y, 0.f);
            h[4 * lane + 2] = fmaxf(ahi.x, 0.f);
            h[4 * lane + 3] = fmaxf(ahi.y, 0.f);
        }
        __syncwarp();
        // layer 2: 128 -> 64, lane owns 2 channels (1 packed pair)
        ull a2p = ld2(&b2s[2 * lane]);
        for (int j = 0; j < 128; j += 4) {
            float4 hv = *(const float4*)&h[j];
            const float* wb = &w2s[j * 64 + 2 * lane];
            fma2(a2p, pk2(hv.x), ld2(wb));
            fma2(a2p, pk2(hv.y), ld2(wb + 64));
            fma2(a2p, pk2(hv.z), ld2(wb + 128));
            fma2(a2p, pk2(hv.w), ld2(wb + 192));
        }
        __syncwarp();
        {
            float2 a2 = upk(a2p);
            f[2 * lane]     = fmaxf(a2.x, 0.f);
            f[2 * lane + 1] = fmaxf(a2.y, 0.f);
        }
        __syncwarp();
        // layer 3: 64 -> 32
        float a3 = b3s[lane];
        for (int j = 0; j < 64; j++) a3 = fmaf(f[j], w3s[j * 32 + lane], a3);
        a3 = fmaxf(a3, 0.f);
        __syncwarp();
        h[lane] = a3;
        __syncwarp();
        // layer 4 + log_softmax (2 classes)
        float o = 0.f;
        if (lane < 2) {
            o = b4s[lane];
            for (int j = 0; j < 32; j++) o = fmaf(h[j], w4s[j * 2 + lane], o);
        }
        float oo = __shfl_xor_sync(0xffffffffu, o, 1);
        if (lane < 2) {
            float mm = fmaxf(o, oo);
            float lse = mm + logf(expf(o - mm) + expf(oo - mm));
            out[(size_t)pt * 2 + lane] = o - lse;
        }
        __syncwarp();
    }
}

// ---------------- launch -------------------------------------------------------
static constexpr size_t EC_SMEM =
    (size_t)(CH * CH + CH + 8 * 8 * CH) * 4 + 8 * KK * 4;
static constexpr size_t MLP_SMEM =
    (size_t)(24576 + 8192 + 2048 + 64 + 128 + 64 + 32 + 4 + 16 * 192 + 16 * 128) * 4;

extern "C" void kernel_launch(void* const* d_in, const int* in_sizes, int n_in,
                              void* d_out, int out_size) {
    (void)in_sizes; (void)n_in; (void)out_size;
    const float* x    = (const float*)d_in[0];
    const float* c1w1 = (const float*)d_in[1];
    const float* c1b1 = (const float*)d_in[2];
    const float* c1w2 = (const float*)d_in[3];
    const float* c1b2 = (const float*)d_in[4];
    const float* c2w1 = (const float*)d_in[5];
    const float* c2b1 = (const float*)d_in[6];
    const float* c2w2 = (const float*)d_in[7];
    const float* c2b2 = (const float*)d_in[8];
    const float* c3w1 = (const float*)d_in[9];
    const float* c3b1 = (const float*)d_in[10];
    const float* c3w2 = (const float*)d_in[11];
    const float* c3b2 = (const float*)d_in[12];
    const float* mw1  = (const float*)d_in[13];
    const float* mb1  = (const float*)d_in[14];
    const float* mw2  = (const float*)d_in[15];
    const float* mb2  = (const float*)d_in[16];
    const float* mw3  = (const float*)d_in[17];
    const float* mb3  = (const float*)d_in[18];
    const float* mw4  = (const float*)d_in[19];
    const float* mb4  = (const float*)d_in[20];
    float* outp = (float*)d_out;

    float *x1p, *x2p, *x3p, *xtp, *basep, *yp;
    int* idxp;
    cudaGetSymbolAddress((void**)&x1p, g_x1);
    cudaGetSymbolAddress((void**)&x2p, g_x2);
    cudaGetSymbolAddress((void**)&x3p, g_x3);
    cudaGetSymbolAddress((void**)&xtp, g_xt);
    cudaGetSymbolAddress((void**)&basep, g_base);
    cudaGetSymbolAddress((void**)&yp, g_y);
    cudaGetSymbolAddress((void**)&idxp, g_idx);

    cudaFuncSetAttribute(edgeconv_kernel,
                         cudaFuncAttributeMaxDynamicSharedMemorySize, (int)EC_SMEM);
    cudaFuncSetAttribute(mlp_kernel,
                         cudaFuncAttributeMaxDynamicSharedMemorySize, (int)MLP_SMEM);

    const int nblk_knt  = BATCH * NPTS / 16;  // 4096 (PB=16)
    const int nblk_ec   = BATCH * NPTS / 32;  // 2048
    const int nblk_yb   = BATCH * NPTS / 64;  // 1024
    const int nblk_tr   = BATCH * (NPTS / 64);// 1024

    knn1_kernel<<<BATCH, 512>>>(x, idxp);
    yb_kernel<1><<<nblk_yb, 256>>>(x, c1w1, c1b1, basep, yp);
    edgeconv_kernel<<<nblk_ec, 256, EC_SMEM>>>(idxp, basep, yp, c1w2, c1b2, x1p);

    transpose_kernel<<<nblk_tr, 256>>>(x1p, xtp);
    knn_t_kernel<<<nblk_knt, 256>>>(xtp, idxp);
    yb_kernel<64><<<nblk_yb, 256>>>(x1p, c2w1, c2b1, basep, yp);
    edgeconv_kernel<<<nblk_ec, 256, EC_SMEM>>>(idxp, basep, yp, c2w2, c2b2, x2p);

    transpose_kernel<<<nblk_tr, 256>>>(x2p, xtp);
    knn_t_kernel<<<nblk_knt, 256>>>(xtp, idxp);
    yb_kernel<64><<<nblk_yb, 256>>>(x2p, c3w1, c3b1, basep, yp);
    edgeconv_kernel<<<nblk_ec, 256, EC_SMEM>>>(idxp, basep, yp, c3w2, c3b2, x3p);

    mlp_kernel<<<148, 512, MLP_SMEM>>>(x1p, x2p, x3p, mw1, mb1, mw2, mb2,
                                       mw3, mb3, mw4, mb4, outp);
}

// round 14
// speedup vs baseline: 1.3381x; 1.0620x over previous
#include <cuda_runtime.h>
#include <math.h>
#include <float.h>
#include <string.h>

#define BATCH 64
#define NPTS  1024
#define KK    16
#define CH    64

typedef unsigned long long ull;

// ---------------- packed f32x2 helpers (R11-measured-neutral; kept there only) --
__device__ __forceinline__ ull pk2(float x) {
    ull r;
    asm("mov.b64 %0, {%1, %1};" : "=l"(r) : "f"(x));
    return r;
}
__device__ __forceinline__ void fma2(ull& d, ull a, ull b) {
    asm("fma.rn.f32x2 %0, %1, %2, %0;" : "+l"(d) : "l"(a), "l"(b));
}
__device__ __forceinline__ float2 upk(ull v) {
    float2 r;
    asm("mov.b64 {%0, %1}, %2;" : "=f"(r.x), "=f"(r.y) : "l"(v));
    return r;
}
__device__ __forceinline__ ull ld2(const float* p) {
    ull r;
    memcpy(&r, p, 8);
    return r;
}

// ---------------- scratch (static device globals; no allocation) ----------------
__device__ __align__(16) float g_x1[BATCH * NPTS * CH];
__device__ __align__(16) float g_x2[BATCH * NPTS * CH];
__device__ __align__(16) float g_x3[BATCH * NPTS * CH];
__device__ __align__(16) float g_xt[BATCH * NPTS * CH];   // transposed features
__device__ __align__(16) float g_sq[BATCH * NPTS];        // per-point sum of squares
__device__ __align__(16) float g_base[BATCH * NPTS * CH]; // b1 + x@w1a - x@w1b
__device__ __align__(16) float g_y[BATCH * NPTS * CH];    // x@w1b
__device__ int g_idx[BATCH * NPTS * KK];

// ---------------- warp bitonic sort of 32 (value,index) pairs, lex ascending ----
__device__ __forceinline__ void bitonic32(float& sv, int& si, int lane) {
#pragma unroll
    for (int size = 2; size <= 32; size <<= 1) {
#pragma unroll
        for (int stride = size >> 1; stride > 0; stride >>= 1) {
            float ov = __shfl_xor_sync(0xffffffffu, sv, stride);
            int oi = __shfl_xor_sync(0xffffffffu, si, stride);
            bool dirDesc = (lane & size) != 0;
            bool iAmLower = (lane & stride) == 0;
            bool wantSmaller = iAmLower != dirDesc;
            bool otherLess = (ov < sv) || (ov == sv && oi < si);
            if (wantSmaller == otherLess) { sv = ov; si = oi; }
        }
    }
}

// ---------------- warp top-16 selection from a 1024 row (exact lex) -------------
__device__ __forceinline__ void warp_select16(float* row, int lane,
                                              int* __restrict__ outp) {
    float v[32];
#pragma unroll
    for (int r = 0; r < 32; r++) v[r] = row[lane + 32 * r];

    float lv = v[0];
    int li = lane;
#pragma unroll
    for (int r = 1; r < 32; r++) {
        if (v[r] < lv) { lv = v[r]; li = lane + 32 * r; }
    }
    float sv = lv; int si = li;
    bitonic32(sv, si, lane);
    float Tv = __shfl_sync(0xffffffffu, sv, 15);
    int   Ti = __shfl_sync(0xffffffffu, si, 15);

    int cnt = 0;
#pragma unroll
    for (int r = 0; r < 32; r++) {
        int idx = lane + 32 * r;
        bool le = (v[r] < Tv) || (v[r] == Tv && idx <= Ti);
        cnt += le ? 1 : 0;
    }
    int total = __reduce_add_sync(0xffffffffu, cnt);

    if (total <= 32) {
        int pre = cnt;
#pragma unroll
        for (int o = 1; o < 32; o <<= 1) {
            int n = __shfl_up_sync(0xffffffffu, pre, o);
            if (lane >= o) pre += n;
        }
        pre -= cnt;
        float* candV = row;
        int* candI = (int*)(row + 32);
        int off = pre;
#pragma unroll
        for (int r = 0; r < 32; r++) {
            int idx = lane + 32 * r;
            bool le = (v[r] < Tv) || (v[r] == Tv && idx <= Ti);
            if (le) { candV[off] = v[r]; candI[off] = idx; off++; }
        }
        __syncwarp();
        float cv = FLT_MAX;
        int ci = 0x7FFFFFFF;
        if (lane < total) { cv = candV[lane]; ci = candI[lane]; }
        bitonic32(cv, ci, lane);
        if (lane < KK) outp[lane] = ci;
    } else {
        for (int k = 0; k < KK; k++) {
            float bv = v[0];
            int br = 0;
#pragma unroll
            for (int r = 1; r < 32; r++) {
                if (v[r] < bv) { bv = v[r]; br = r; }
            }
            int bi = lane + 32 * br;
#pragma unroll
            for (int o = 16; o > 0; o >>= 1) {
                float ov = __shfl_xor_sync(0xffffffffu, bv, o);
                int oi = __shfl_xor_sync(0xffffffffu, bi, o);
                if (ov < bv || (ov == bv && oi < bi)) { bv = ov; bi = oi; }
            }
            if (lane == 0) outp[k] = bi;
            if ((bi & 31) == lane) {
                int rr = bi >> 5;
#pragma unroll
                for (int r = 0; r < 32; r++)
                    if (r == rr) v[r] = FLT_MAX;
            }
        }
    }
}

// ---------------- kNN (D=1): sort-based window selection ------------------------
__global__ void __launch_bounds__(512) knn1_kernel(const float* __restrict__ x,
                                                   int* __restrict__ idx_out) {
    __shared__ float sv[NPTS];
    __shared__ int si[NPTS];
    const int b = blockIdx.x;
    const int tid = threadIdx.x;  // 512

    for (int t = tid; t < NPTS; t += 512) {
        sv[t] = x[(size_t)b * NPTS + t];
        si[t] = t;
    }
    __syncthreads();

    for (int size = 2; size <= NPTS; size <<= 1) {
        for (int stride = size >> 1; stride > 0; stride >>= 1) {
            int i = ((tid & ~(stride - 1)) << 1) | (tid & (stride - 1));
            int j = i | stride;
            float va = sv[i], vb = sv[j];
            int ia = si[i], ib = si[j];
            bool agtb = (va > vb) || (va == vb && ia > ib);
            bool asc = ((i & size) == 0);
            if (agtb == asc) { sv[i] = vb; si[i] = ib; sv[j] = va; si[j] = ia; }
            __syncthreads();
        }
    }

    const int w = tid >> 5, lane = tid & 31;
    for (int r = w * 64; r < w * 64 + 64; r++) {
        float xi = sv[r];
        int q = r - 15 + lane;
        bool valid = (q >= 0) && (q < NPTS);
        float cv = FLT_MAX;
        int ci = 0x7FFFFFFF;
        if (valid) {
            float xj = sv[q];
            cv = (xi * xi + xj * xj) - 2.f * (xi * xj);
            ci = si[q];
        }
        bitonic32(cv, ci, lane);
        int orig = si[r];
        if (lane < KK)
            idx_out[((size_t)(b * NPTS + orig)) * KK + lane] = ci;
    }
}

// ---------------- transpose + per-point sum-of-squares ---------------------------
// [NPTS, CH] -> [CH, NPTS] per batch; also emits sq[i] = sum_c x[i,c]^2.
__global__ void __launch_bounds__(256) transpose_kernel(const float* __restrict__ feat,
                                                        float* __restrict__ featT,
                                                        float* __restrict__ sqo) {
    __shared__ float tile[64 * 65];
    const int tid = threadIdx.x;
    const int bpB = NPTS / 64;
    const int b = blockIdx.x / bpB;
    const int row0 = (blockIdx.x % bpB) * 64;
    const float* fb = feat + ((size_t)b * NPTS + row0) * CH;
    for (int t = tid; t < 64 * 64; t += 256) {
        int r = t >> 6, c = t & 63;
        tile[c * 65 + r] = fb[r * CH + c];
    }
    __syncthreads();
    float* ob = featT + (size_t)b * CH * NPTS + row0;
    for (int t = tid; t < 64 * 64; t += 256) {
        int c = t >> 6, r = t & 63;
        ob[(size_t)c * NPTS + r] = tile[c * 65 + r];
    }
    // sq: threads 0..63 each reduce one point's 64 channels (stride-65, conflict-free)
    if (tid < 64) {
        float s = 0.f;
        for (int c = 0; c < 64; c++) {
            float v = tile[c * 65 + tid];
            s = fmaf(v, v, s);
        }
        sqo[(size_t)b * NPTS + row0 + tid] = s;
    }
}

// ---------------- kNN (CH=64): coalesced, precomputed sq (R11 form minus sqj) ---
__global__ void __launch_bounds__(256, 4) knn_t_kernel(const float* __restrict__ featT,
                                                       const float* __restrict__ sqp,
                                                       int* __restrict__ idx_out) {
    constexpr int PB = 8;
    __shared__ __align__(16) float dist[PB][NPTS];
    __shared__ __align__(16) float xqT[CH * PB];
    __shared__ float sqi[PB];

    const int tid = threadIdx.x;
    const int gbase = blockIdx.x * PB;
    const int b = gbase / NPTS;
    const int i0 = gbase % NPTS;
    const float* ftb = featT + (size_t)b * CH * NPTS;
    const float* sqb = sqp + (size_t)b * NPTS;

    for (int t = tid; t < CH * PB; t += 256) {
        int c = t >> 3, p = t & 7;
        xqT[t] = ftb[(size_t)c * NPTS + i0 + p];
    }
    if (tid < PB) sqi[tid] = sqb[i0 + tid];
    __syncthreads();

    const float4* ft4 = (const float4*)ftb;
    float dot[PB][4];
#pragma unroll
    for (int p = 0; p < PB; p++)
#pragma unroll
        for (int jj = 0; jj < 4; jj++) dot[p][jj] = 0.f;

    for (int c = 0; c < CH; c++) {
        float4 v = ft4[c * (NPTS / 4) + tid];
        float4 q0 = *(const float4*)&xqT[c * 8];
        float4 q1 = *(const float4*)&xqT[c * 8 + 4];
        float q[8] = {q0.x, q0.y, q0.z, q0.w, q1.x, q1.y, q1.z, q1.w};
#pragma unroll
        for (int p = 0; p < PB; p++) {
            dot[p][0] = fmaf(v.x, q[p], dot[p][0]);
            dot[p][1] = fmaf(v.y, q[p], dot[p][1]);
            dot[p][2] = fmaf(v.z, q[p], dot[p][2]);
            dot[p][3] = fmaf(v.w, q[p], dot[p][3]);
        }
    }
    const int j0 = tid * 4;
    float4 sqj = *(const float4*)&sqb[j0];
#pragma unroll
    for (int p = 0; p < PB; p++) {
        float4 dv;
        dv.x = sqi[p] + sqj.x - 2.f * dot[p][0];
        dv.y = sqi[p] + sqj.y - 2.f * dot[p][1];
        dv.z = sqi[p] + sqj.z - 2.f * dot[p][2];
        dv.w = sqi[p] + sqj.w - 2.f * dot[p][3];
        *(float4*)&dist[p][j0] = dv;
    }
    __syncthreads();

    const int g = tid >> 5, lane = tid & 31;
    warp_select16(dist[g], lane, &idx_out[((size_t)(b * NPTS + i0 + g)) * KK]);
}

// ---------------- Y/base precompute -------------------------------------------
template <int D>
__global__ void __launch_bounds__(256) yb_kernel(
    const float* __restrict__ feat, const float* __restrict__ w1,
    const float* __restrict__ b1, float* __restrict__ baseo,
    float* __restrict__ yo) {
    __shared__ float w1as[D * CH];
    __shared__ float w1bs[D * CH];
    __shared__ float b1s[CH];
    const int tid = threadIdx.x, p = tid >> 5, lane = tid & 31;
    for (int t = tid; t < D * CH; t += 256) {
        w1as[t] = w1[t];
        w1bs[t] = w1[D * CH + t];
    }
    if (tid < CH) b1s[tid] = b1[tid];
    __syncthreads();
    const int k0 = 2 * lane;
    for (int g = 0; g < 8; g++) {
        int i = blockIdx.x * 64 + g * 8 + p;
        const float* fx = feat + (size_t)i * D;
        float zx = 0.f, zy = 0.f, yx = 0.f, yy = 0.f;
        if constexpr (D == 1) {
            float xv = fx[0];
            float2 wa = *(const float2*)&w1as[k0];
            float2 wb = *(const float2*)&w1bs[k0];
            zx = xv * wa.x; zy = xv * wa.y;
            yx = xv * wb.x; yy = xv * wb.y;
        } else {
            float xr[D / 32];
#pragma unroll
            for (int h = 0; h < D / 32; h++) xr[h] = fx[h * 32 + lane];
#pragma unroll
            for (int h = 0; h < D / 32; h++) {
                for (int j = 0; j < 32; j++) {
                    float xv = __shfl_sync(0xffffffffu, xr[h], j);
                    float2 wa = *(const float2*)&w1as[(h * 32 + j) * CH + k0];
                    float2 wb = *(const float2*)&w1bs[(h * 32 + j) * CH + k0];
                    zx = fmaf(xv, wa.x, zx); zy = fmaf(xv, wa.y, zy);
                    yx = fmaf(xv, wb.x, yx); yy = fmaf(xv, wb.y, yy);
                }
            }
        }
        *(float2*)&baseo[(size_t)i * CH + k0] =
            make_float2(b1s[k0] + zx - yx, b1s[k0 + 1] + zy - yy);
        *(float2*)&yo[(size_t)i * CH + k0] = make_float2(yx, yy);
    }
}

// ---------------- EdgeConv: h1 = relu(base_i + Y_j); out = max_k h1@w2 + b2 -----
// (R11 form: FFMA2 stage-2 with channel-pair acc; measured best)
__global__ void __launch_bounds__(256, 4) edgeconv_kernel(
    const int* __restrict__ idx, const float* __restrict__ basep,
    const float* __restrict__ yp, const float* __restrict__ w2,
    const float* __restrict__ b2, float* __restrict__ out) {
    constexpr int PTS = 8;
    constexpr int NB = 8;
    constexpr int GROUPS = 4;
    extern __shared__ float s[];
    float* w2s = s;
    float* b2s = w2s + CH * CH;
    float* ys  = b2s + CH;
    int* nbr   = (int*)(ys + PTS * NB * CH);

    const int tid = threadIdx.x;
    const int p = tid >> 5, lane = tid & 31;

    for (int t = tid; t < CH * CH; t += 256) w2s[t] = w2[t];
    if (tid < CH) b2s[tid] = b2[tid];
    __syncthreads();

    const int k0 = 2 * lane;

    for (int grp = 0; grp < GROUPS; grp++) {
        const int gbase = blockIdx.x * (PTS * GROUPS) + grp * PTS;
        const int b = gbase / NPTS;
        const int i = (gbase % NPTS) + p;
        const int gi = b * NPTS + i;
        const float* yb = yp + (size_t)b * NPTS * CH;

        if (lane < KK) nbr[p * KK + lane] = idx[(size_t)gi * KK + lane];
        __syncwarp();

        float2 bse = *(const float2*)&basep[(size_t)gi * CH + k0];
        float bx = bse.x, by = bse.y;
        float mx = -FLT_MAX, my = -FLT_MAX;

        for (int c0 = 0; c0 < KK; c0 += NB) {
            for (int t = lane; t < NB * (CH / 4); t += 32) {
                int nb = t >> 4, c4 = t & 15;
                float4 vv = *(const float4*)(yb +
                    (size_t)nbr[p * KK + c0 + nb] * CH + 4 * c4);
                *(float4*)&ys[(p * NB + nb) * CH + 4 * c4] = vv;
            }
            __syncwarp();

#pragma unroll
            for (int nb = 0; nb < NB; nb++) {
                float2 h = *(const float2*)&ys[(p * NB + nb) * CH + k0];
                h.x = fmaxf(bx + h.x, 0.f);
                h.y = fmaxf(by + h.y, 0.f);
                *(float2*)&ys[(p * NB + nb) * CH + k0] = h;
            }
            __syncwarp();

            ull acc2[NB];
#pragma unroll
            for (int nb = 0; nb < NB; nb++) acc2[nb] = 0ull;
            const float* hbase = &ys[p * NB * CH];
            for (int j = 0; j < CH; j += 4) {
                const float* wb = &w2s[j * CH + k0];
                ull w0 = ld2(wb);
                ull w1 = ld2(wb + CH);
                ull w2v = ld2(wb + 2 * CH);
                ull w3v = ld2(wb + 3 * CH);
#pragma unroll
                for (int nb = 0; nb < NB; nb++) {
                    float4 hv = *(const float4*)(hbase + nb * CH + j);
                    fma2(acc2[nb], pk2(hv.x), w0);
                    fma2(acc2[nb], pk2(hv.y), w1);
                    fma2(acc2[nb], pk2(hv.z), w2v);
                    fma2(acc2[nb], pk2(hv.w), w3v);
                }
            }
#pragma unroll
            for (int nb = 0; nb < NB; nb++) {
                float2 a = upk(acc2[nb]);
                mx = fmaxf(mx, a.x);
                my = fmaxf(my, a.y);
            }
            __syncwarp();
        }

        size_t ob = (size_t)gi * CH;
        out[ob + k0]     = mx + b2s[k0];
        out[ob + k0 + 1] = my + b2s[k0 + 1];
    }
}

// ---------------- final MLP: 192 -> 128 -> 64 -> 32 -> 2, log_softmax ------------
__global__ void __launch_bounds__(512) mlp_kernel(
    const float* __restrict__ x1, const float* __restrict__ x2,
    const float* __restrict__ x3,
    const float* __restrict__ mw1, const float* __restrict__ mb1,
    const float* __restrict__ mw2, const float* __restrict__ mb2,
    const float* __restrict__ mw3, const float* __restrict__ mb3,
    const float* __restrict__ mw4, const float* __restrict__ mb4,
    float* __restrict__ out) {
    extern __shared__ float s[];
    float* w1s = s;
    float* w2s = w1s + 24576;
    float* w3s = w2s + 8192;
    float* w4s = w3s + 2048;
    float* b1s = w4s + 64;
    float* b2s = b1s + 128;
    float* b3s = b2s + 64;
    float* b4s = b3s + 32;
    float* fbuf = b4s + 4;
    float* hbuf = fbuf + 16 * 192;

    const int tid = threadIdx.x;
    const int w = tid >> 5, lane = tid & 31;
    for (int t = tid; t < 24576; t += 512) w1s[t] = mw1[t];
    for (int t = tid; t < 8192; t += 512) w2s[t] = mw2[t];
    for (int t = tid; t < 2048; t += 512) w3s[t] = mw3[t];
    if (tid < 64) w4s[tid] = mw4[tid];
    if (tid < 128) b1s[tid] = mb1[tid];
    if (tid < 64) b2s[tid] = mb2[tid];
    if (tid < 32) b3s[tid] = mb3[tid];
    if (tid < 2) b4s[tid] = mb4[tid];
    __syncthreads();

    const int total = BATCH * NPTS;
    const int ptsPerBlock = (total + gridDim.x - 1) / gridDim.x;
    const int pbase = blockIdx.x * ptsPerBlock;
    const int pend = min(pbase + ptsPerBlock, total);
    float* f = fbuf + w * 192;
    float* h = hbuf + w * 128;

    for (int pt = pbase + w; pt < pend; pt += 16) {
        for (int t = lane; t < 64; t += 32) {
            f[t]       = x1[(size_t)pt * 64 + t];
            f[64 + t]  = x2[(size_t)pt * 64 + t];
            f[128 + t] = x3[(size_t)pt * 64 + t];
        }
        __syncwarp();
        // layer 1: 192 -> 128, lane owns 4 channels (2 packed pairs)
        ull a1lo = ld2(&b1s[4 * lane]);
        ull a1hi = ld2(&b1s[4 * lane + 2]);
        for (int j = 0; j < 192; j += 4) {
            float4 xv = *(const float4*)&f[j];
            const float* wb = &w1s[j * 128 + 4 * lane];
            float4 w0 = *(const float4*)(wb);
            float4 w1v = *(const float4*)(wb + 128);
            float4 w2v = *(const float4*)(wb + 256);
            float4 w3v = *(const float4*)(wb + 384);
            ull xx;
            xx = pk2(xv.x);
            { ull wl, wh; memcpy(&wl, &w0.x, 8); memcpy(&wh, &w0.z, 8);
              fma2(a1lo, xx, wl); fma2(a1hi, xx, wh); }
            xx = pk2(xv.y);
            { ull wl, wh; memcpy(&wl, &w1v.x, 8); memcpy(&wh, &w1v.z, 8);
              fma2(a1lo, xx, wl); fma2(a1hi, xx, wh); }
            xx = pk2(xv.z);
            { ull wl, wh; memcpy(&wl, &w2v.x, 8); memcpy(&wh, &w2v.z, 8);
              fma2(a1lo, xx, wl); fma2(a1hi, xx, wh); }
            xx = pk2(xv.w);
            { ull wl, wh; memcpy(&wl, &w3v.x, 8); memcpy(&wh, &w3v.z, 8);
              fma2(a1lo, xx, wl); fma2(a1hi, xx, wh); }
        }
        {
            float2 alo = upk(a1lo), ahi = upk(a1hi);
            h[4 * lane]     = fmaxf(alo.x, 0.f);
            h[4 * lane + 1] = fmaxf(alo.y, 0.f);
            h[4 * lane + 2] = fmaxf(ahi.x, 0.f);
            h[4 * lane + 3] = fmaxf(ahi.y, 0.f);
        }
        __syncwarp();
        // layer 2: 128 -> 64, lane owns 2 channels (1 packed pair)
        ull a2p = ld2(&b2s[2 * lane]);
        for (int j = 0; j < 128; j += 4) {
            float4 hv = *(const float4*)&h[j];
            const float* wb = &w2s[j * 64 + 2 * lane];
            fma2(a2p, pk2(hv.x), ld2(wb));
            fma2(a2p, pk2(hv.y), ld2(wb + 64));
            fma2(a2p, pk2(hv.z), ld2(wb + 128));
            fma2(a2p, pk2(hv.w), ld2(wb + 192));
        }
        __syncwarp();
        {
            float2 a2 = upk(a2p);
            f[2 * lane]     = fmaxf(a2.x, 0.f);
            f[2 * lane + 1] = fmaxf(a2.y, 0.f);
        }
        __syncwarp();
        // layer 3: 64 -> 32
        float a3 = b3s[lane];
        for (int j = 0; j < 64; j++) a3 = fmaf(f[j], w3s[j * 32 + lane], a3);
        a3 = fmaxf(a3, 0.f);
        __syncwarp();
        h[lane] = a3;
        __syncwarp();
        // layer 4 + log_softmax (2 classes)
        float o = 0.f;
        if (lane < 2) {
            o = b4s[lane];
            for (int j = 0; j < 32; j++) o = fmaf(h[j], w4s[j * 2 + lane], o);
        }
        float oo = __shfl_xor_sync(0xffffffffu, o, 1);
        if (lane < 2) {
            float mm = fmaxf(o, oo);
            float lse = mm + logf(expf(o - mm) + expf(oo - mm));
            out[(size_t)pt * 2 + lane] = o - lse;
        }
        __syncwarp();
    }
}

// ---------------- launch -------------------------------------------------------
static constexpr size_t EC_SMEM =
    (size_t)(CH * CH + CH + 8 * 8 * CH) * 4 + 8 * KK * 4;
static constexpr size_t MLP_SMEM =
    (size_t)(24576 + 8192 + 2048 + 64 + 128 + 64 + 32 + 4 + 16 * 192 + 16 * 128) * 4;

extern "C" void kernel_launch(void* const* d_in, const int* in_sizes, int n_in,
                              void* d_out, int out_size) {
    (void)in_sizes; (void)n_in; (void)out_size;
    const float* x    = (const float*)d_in[0];
    const float* c1w1 = (const float*)d_in[1];
    const float* c1b1 = (const float*)d_in[2];
    const float* c1w2 = (const float*)d_in[3];
    const float* c1b2 = (const float*)d_in[4];
    const float* c2w1 = (const float*)d_in[5];
    const float* c2b1 = (const float*)d_in[6];
    const float* c2w2 = (const float*)d_in[7];
    const float* c2b2 = (const float*)d_in[8];
    const float* c3w1 = (const float*)d_in[9];
    const float* c3b1 = (const float*)d_in[10];
    const float* c3w2 = (const float*)d_in[11];
    const float* c3b2 = (const float*)d_in[12];
    const float* mw1  = (const float*)d_in[13];
    const float* mb1  = (const float*)d_in[14];
    const float* mw2  = (const float*)d_in[15];
    const float* mb2  = (const float*)d_in[16];
    const float* mw3  = (const float*)d_in[17];
    const float* mb3  = (const float*)d_in[18];
    const float* mw4  = (const float*)d_in[19];
    const float* mb4  = (const float*)d_in[20];
    float* outp = (float*)d_out;

    float *x1p, *x2p, *x3p, *xtp, *sqp, *basep, *yp;
    int* idxp;
    cudaGetSymbolAddress((void**)&x1p, g_x1);
    cudaGetSymbolAddress((void**)&x2p, g_x2);
    cudaGetSymbolAddress((void**)&x3p, g_x3);
    cudaGetSymbolAddress((void**)&xtp, g_xt);
    cudaGetSymbolAddress((void**)&sqp, g_sq);
    cudaGetSymbolAddress((void**)&basep, g_base);
    cudaGetSymbolAddress((void**)&yp, g_y);
    cudaGetSymbolAddress((void**)&idxp, g_idx);

    cudaFuncSetAttribute(edgeconv_kernel,
                         cudaFuncAttributeMaxDynamicSharedMemorySize, (int)EC_SMEM);
    cudaFuncSetAttribute(mlp_kernel,
                         cudaFuncAttributeMaxDynamicSharedMemorySize, (int)MLP_SMEM);

    const int nblk_knn  = BATCH * NPTS / 8;   // 8192
    const int nblk_ec   = BATCH * NPTS / 32;  // 2048
    const int nblk_yb   = BATCH * NPTS / 64;  // 1024
    const int nblk_tr   = BATCH * (NPTS / 64);// 1024

    knn1_kernel<<<BATCH, 512>>>(x, idxp);
    yb_kernel<1><<<nblk_yb, 256>>>(x, c1w1, c1b1, basep, yp);
    edgeconv_kernel<<<nblk_ec, 256, EC_SMEM>>>(idxp, basep, yp, c1w2, c1b2, x1p);

    transpose_kernel<<<nblk_tr, 256>>>(x1p, xtp, sqp);
    knn_t_kernel<<<nblk_knn, 256>>>(xtp, sqp, idxp);
    yb_kernel<64><<<nblk_yb, 256>>>(x1p, c2w1, c2b1, basep, yp);
    edgeconv_kernel<<<nblk_ec, 256, EC_SMEM>>>(idxp, basep, yp, c2w2, c2b2, x2p);

    transpose_kernel<<<nblk_tr, 256>>>(x2p, xtp, sqp);
    knn_t_kernel<<<nblk_knn, 256>>>(xtp, sqp, idxp);
    yb_kernel<64><<<nblk_yb, 256>>>(x2p, c3w1, c3b1, basep, yp);
    edgeconv_kernel<<<nblk_ec, 256, EC_SMEM>>>(idxp, basep, yp, c3w2, c3b2, x3p);

    mlp_kernel<<<148, 512, MLP_SMEM>>>(x1p, x2p, x3p, mw1, mb1, mw2, mb2,
                                       mw3, mb3, mw4, mb4, outp);
}